// round 17
// baseline (speedup 1.0000x reference)
#include <cuda_runtime.h>

#define FULL 0xffffffffu
typedef unsigned long long u64;
constexpr int NW = 10;   // wires
constexpr int NL = 4;    // layers

// Layer-1 fused gate bases: G = RY(th) * RZ(phi) (om pushed into phase tables)
__device__ float4 g_rot[NW * 2];
// Layers 2-4 RY coefficients: (cos(th/2), sin(th/2))
__device__ float2 g_rycs[3 * NW];
// Phase tables Gamma_g (g=0..2), stored permuted by the accumulated lane
// relabeling M_{g+1} and transposed [k][bufferLane].
// g_phA = (cr0,cr1 | -ci0,-ci1) as ulonglong2, g_phB = (ci0,ci1) as u64.
__device__ ulonglong2 g_phA[3 * 512];
__device__ u64 g_phB[3 * 512];

// ---------------------------------------------------------------------------
// Prep
// ---------------------------------------------------------------------------
__device__ __forceinline__ u64 h_pack(float x, float y) {
    u64 d;
    asm("mov.b64 %0, {%1, %2};" : "=l"(d) : "f"(x), "f"(y));
    return d;
}

__global__ void prep_kernel(const float* __restrict__ w) {
    __shared__ float s_ang[1024], s_co[1024], s_si[1024];
    int v = threadIdx.x;

    if (v < NL * NW) {
        int l = v / NW, wi = v % NW;
        float phi = w[v * 3 + 0], th = w[v * 3 + 1];
        float s, c;
        sincosf(0.5f * th, &s, &c);
        if (l == 0) {
            float sp, cp;  // e^{-i phi/2}
            sincosf(-0.5f * phi, &sp, &cp);
            g_rot[wi * 2 + 0] = make_float4(c * cp, c * sp, -s * cp, s * sp);
            g_rot[wi * 2 + 1] = make_float4(s * cp, s * sp, c * cp, -c * sp);
        } else {
            g_rycs[(l - 1) * NW + wi] = make_float2(c, s);
        }
    }

    // Rows of M_{g+1}^{-1} (buffer lane from true lane): l_b = parity(row_b & L)
    const int MinvR[3][5] = {{3, 6, 12, 24, 16},
                             {15, 30, 28, 24, 16},
                             {23, 14, 28, 24, 16}};

    for (int g = 0; g < 3; ++g) {
        __syncthreads();
        // delta1 (RZ(om) of layer g) pushed through FULL ring r=g+1 (circuit level)
        float a1 = 0.0f;
#pragma unroll
        for (int wi = 0; wi < NW; ++wi) {
            float om = w[(g * NW + wi) * 3 + 2];
            a1 += (((v >> (9 - wi)) & 1) ? 0.5f : -0.5f) * om;
        }
        int u = v, r = g + 1;
#pragma unroll
        for (int wi = 0; wi < NW; ++wi) {
            int pc = 9 - wi, pt = 9 - ((wi + r) % NW);
            if ((u >> pc) & 1) u ^= (1 << pt);
        }
        s_ang[u] = a1;
        __syncthreads();
        float a = s_ang[v];
#pragma unroll
        for (int wi = 0; wi < NW; ++wi) {
            float phi = w[((g + 1) * NW + wi) * 3 + 0];
            a += (((v >> (9 - wi)) & 1) ? 0.5f : -0.5f) * phi;
        }
        float si, co;
        sincosf(a, &si, &co);
        s_co[v] = co;
        s_si[v] = si;
        __syncthreads();
        if (v < 512) {
            int v0 = 2 * v, v1 = 2 * v + 1;
            int k = v & 15, L = v >> 4;   // true lane part L
            int l = 0;                    // buffer lane = Minv(L)
#pragma unroll
            for (int b = 0; b < 5; ++b)
                l |= (__popc(MinvR[g][b] & L) & 1) << b;
            int idx = (k << 5) | l;
            ulonglong2 A;
            A.x = h_pack(s_co[v0], s_co[v1]);
            A.y = h_pack(-s_si[v0], -s_si[v1]);
            g_phA[g * 512 + idx] = A;
            g_phB[g * 512 + idx] = h_pack(s_si[v0], s_si[v1]);
        }
    }
}

// ---------------------------------------------------------------------------
// Packed f32x2 helpers — state in aligned 64-bit register pairs
// ---------------------------------------------------------------------------
__device__ __forceinline__ u64 ffma2(u64 a, u64 b, u64 c) {
    u64 d;
    asm("fma.rn.f32x2 %0, %1, %2, %3;" : "=l"(d) : "l"(a), "l"(b), "l"(c));
    return d;
}
__device__ __forceinline__ u64 fmul2(u64 a, u64 b) {
    u64 d;
    asm("mul.rn.f32x2 %0, %1, %2;" : "=l"(d) : "l"(a), "l"(b));
    return d;
}
__device__ __forceinline__ u64 pk2(float x, float y) {
    u64 d;
    asm("mov.b64 %0, {%1, %2};" : "=l"(d) : "f"(x), "f"(y));
    return d;
}
__device__ __forceinline__ u64 pk(float v) { return pk2(v, v); }
__device__ __forceinline__ float2 unpk(u64 a) {
    float2 r;
    asm("mov.b64 {%0, %1}, %2;" : "=f"(r.x), "=f"(r.y) : "l"(a));
    return r;
}
__device__ __forceinline__ u64 swp64(u64 a) {
    float2 t = unpk(a);
    return pk2(t.y, t.x);
}
__device__ __forceinline__ u64 shx64(u64 v, int mask) {
    float2 t = unpk(v);
    t.x = __shfl_xor_sync(FULL, t.x, mask);
    t.y = __shfl_xor_sync(FULL, t.y, mask);
    return pk2(t.x, t.y);
}
__device__ __forceinline__ float2 cmulf(float2 a, float2 b) {
    return make_float2(a.x * b.x - a.y * b.y, a.x * b.y + a.y * b.x);
}

// ---------------------------------------------------------------------------
// Buffer layout: amp = (bufLane:5 | k:4 | half:1); true lane = M * bufLane.
// ---------------------------------------------------------------------------

__device__ __forceinline__ void colF(int W, float myc, float mys,
                                     float2& F00, float2& F10) {
    float cw = __shfl_sync(FULL, myc, W);
    float sw = __shfl_sync(FULL, mys, W);
    float4 g0 = g_rot[W * 2 + 0];
    float4 g1 = g_rot[W * 2 + 1];
    F00 = make_float2(fmaf(g0.x, cw, g0.z * sw), fmaf(g0.y, cw, g0.w * sw));
    F10 = make_float2(fmaf(g1.x, cw, g1.z * sw), fmaf(g1.y, cw, g1.w * sw));
}

// Build the post-layer-1 product state directly (layout M = I).
__device__ __forceinline__ void buildInit(u64 RE[16], u64 IM[16], int lane,
                                          float myc, float mys) {
    float2 F00, F10;
    colF(0, myc, mys, F00, F10);
    float2 L = ((lane >> 4) & 1) ? F10 : F00;
#pragma unroll
    for (int W = 1; W < 5; ++W) {
        colF(W, myc, mys, F00, F10);
        float2 pick = ((lane >> (4 - W)) & 1) ? F10 : F00;
        L = cmulf(L, pick);
    }
    colF(9, myc, mys, F00, F10);
    float2 a0 = cmulf(L, F00), a1 = cmulf(L, F10);
    RE[0] = pk2(a0.x, a1.x);
    IM[0] = pk2(a0.y, a1.y);
#pragma unroll
    for (int W = 8; W >= 5; --W) {
        colF(W, myc, mys, F00, F10);
        const int kb = 1 << (8 - W);
        const u64 c00 = pk(F00.x), s00 = pk(F00.y), n00 = pk(-F00.y);
        const u64 c10 = pk(F10.x), s10 = pk(F10.y), n10 = pk(-F10.y);
#pragma unroll
        for (int k = 0; k < 16; ++k) {
            if (k < kb) {
                u64 r = RE[k], i = IM[k];
                RE[k | kb] = ffma2(c10, r, fmul2(n10, i));
                IM[k | kb] = ffma2(c10, i, fmul2(s10, r));
                RE[k] = ffma2(c00, r, fmul2(n00, i));
                IM[k] = ffma2(c00, i, fmul2(s00, r));
            }
        }
    }
}

// ---------------------------------------------------------------------------
// RY gate primitives (relabeling-aware)
// ---------------------------------------------------------------------------
// Lane RY: partner = bufLane ^ X, side = parity(bufLane & B)
template <int X, int B>
__device__ __forceinline__ void ryLaneP(u64 RE[16], u64 IM[16], int lane,
                                        float c, float s) {
    float sg = (__popc(lane & B) & 1) ? s : -s;
    const u64 cp = pk(c), sp = pk(sg);
#pragma unroll
    for (int k = 0; k < 16; ++k) {
        u64 ore = shx64(RE[k], X);
        u64 oim = shx64(IM[k], X);
        RE[k] = ffma2(cp, RE[k], fmul2(sp, ore));
        IM[k] = ffma2(cp, IM[k], fmul2(sp, oim));
    }
}
// Local RY across register bit KB
template <int KB>
__device__ __forceinline__ void ryLocalK(u64 RE[16], u64 IM[16], float c, float s) {
    const u64 cp = pk(c), sp = pk(s), np = pk(-s);
#pragma unroll
    for (int k = 0; k < 16; ++k) {
        if (!(k & KB)) {
            const int j = k | KB;
            u64 a0re = RE[k], a0im = IM[k], a1re = RE[j], a1im = IM[j];
            RE[k] = ffma2(cp, a0re, fmul2(np, a1re));
            IM[k] = ffma2(cp, a0im, fmul2(np, a1im));
            RE[j] = ffma2(cp, a1re, fmul2(sp, a0re));
            IM[j] = ffma2(cp, a1im, fmul2(sp, a0im));
        }
    }
}
// Half-bit RY
__device__ __forceinline__ void ryHalf(u64 RE[16], u64 IM[16], float c, float s) {
    const u64 cp = pk(c), ss = pk2(-s, s);
#pragma unroll
    for (int k = 0; k < 16; ++k) {
        RE[k] = ffma2(cp, RE[k], fmul2(ss, swp64(RE[k])));
        IM[k] = ffma2(cp, IM[k], fmul2(ss, swp64(IM[k])));
    }
}

// Gamma (composed diagonal), table permuted by active M at prep
__device__ __forceinline__ void applyPhase(u64 RE[16], u64 IM[16], int lane, int g) {
    const ulonglong2* __restrict__ A = g_phA + g * 512 + lane;
    const u64* __restrict__ Bv = g_phB + g * 512 + lane;
#pragma unroll
    for (int k = 0; k < 16; ++k) {
        ulonglong2 a = A[k << 5];
        u64 ci = Bv[k << 5];
        u64 nre = ffma2(a.x, RE[k], fmul2(a.y, IM[k]));
        u64 nim = ffma2(a.x, IM[k], fmul2(ci, RE[k]));
        RE[k] = nre; IM[k] = nim;
    }
}

// ---------------------------------------------------------------------------
// CNOT primitives
// ---------------------------------------------------------------------------
template <int TM>
__device__ __forceinline__ void predSwapK(u64 RE[16], u64 IM[16], bool c1) {
#pragma unroll
    for (int k = 0; k < 16; ++k) {
        if (!(k & TM)) {
            u64 a = RE[k], b = RE[k | TM];
            RE[k] = c1 ? b : a; RE[k | TM] = c1 ? a : b;
            u64 e = IM[k], f = IM[k | TM];
            IM[k] = c1 ? f : e; IM[k | TM] = c1 ? e : f;
        }
    }
}
template <int CM, int TM>
__device__ __forceinline__ void localCnot(u64 RE[16], u64 IM[16]) {
#pragma unroll
    for (int k = 0; k < 16; ++k) {
        if ((k & CM) && !(k & TM)) {
            u64 a = RE[k]; RE[k] = RE[k | TM]; RE[k | TM] = a;
            u64 b = IM[k]; IM[k] = IM[k | TM]; IM[k | TM] = b;
        }
    }
}
template <int CM>
__device__ __forceinline__ void ctrlK_swpHalf(u64 RE[16], u64 IM[16]) {
#pragma unroll
    for (int k = 0; k < 16; ++k) {
        if (k & CM) { RE[k] = swp64(RE[k]); IM[k] = swp64(IM[k]); }
    }
}
template <int CM, int X>
__device__ __forceinline__ void ctrlK_laneShfl(u64 RE[16], u64 IM[16]) {
#pragma unroll
    for (int k = 0; k < 16; ++k) {
        if (k & CM) { RE[k] = shx64(RE[k], X); IM[k] = shx64(IM[k], X); }
    }
}
template <int X>
__device__ __forceinline__ void halfCtrl_laneShfl(u64 RE[16], u64 IM[16]) {
#pragma unroll
    for (int k = 0; k < 16; ++k) {
        float2 r = unpk(RE[k]);
        r.y = __shfl_xor_sync(FULL, r.y, X);
        RE[k] = pk2(r.x, r.y);
        float2 i = unpk(IM[k]);
        i.y = __shfl_xor_sync(FULL, i.y, X);
        IM[k] = pk2(i.x, i.y);
    }
}

// ---------------------------------------------------------------------------
// Rings — lane-lane composed blocks deferred into lane relabeling M; only the
// remaining physical gates with buffer-space masks (constants proven in R8).
// ---------------------------------------------------------------------------
// Ring 1, under M1
__device__ __forceinline__ void ring1(u64 RE[16], u64 IM[16], int lane) {
    predSwapK<8>(RE, IM, __popc(lane & 31) & 1);  // w4: CNOT(4,5)
    localCnot<8, 4>(RE, IM);                      // w5: CNOT(5,6)
    localCnot<4, 2>(RE, IM);                      // w6: CNOT(6,7)
    localCnot<2, 1>(RE, IM);                      // w7: CNOT(7,8)
    ctrlK_swpHalf<1>(RE, IM);                     // w8: CNOT(8,9)
    halfCtrl_laneShfl<24>(RE, IM);                // w9: CNOT(9,0)
}
// Ring 2, under M2
__device__ __forceinline__ void ring2(u64 RE[16], u64 IM[16], int lane) {
    predSwapK<8>(RE, IM, __popc(lane & 6) & 1);   // w3: CNOT(3,5)
    predSwapK<4>(RE, IM, __popc(lane & 19) & 1);  // w4: CNOT(4,6)
    localCnot<8, 2>(RE, IM);                      // w5: CNOT(5,7)
    localCnot<4, 1>(RE, IM);                      // w6: CNOT(6,8)
    ctrlK_swpHalf<2>(RE, IM);                     // w7: CNOT(7,9)
    ctrlK_laneShfl<1, 30>(RE, IM);                // w8: CNOT(8,0)
    halfCtrl_laneShfl<15>(RE, IM);                // w9: CNOT(9,1)
}
// Ring 3, under M3
__device__ __forceinline__ void ring3(u64 RE[16], u64 IM[16], int lane) {
    predSwapK<8>(RE, IM, __popc(lane & 12) & 1);  // w2: CNOT(2,5)
    predSwapK<4>(RE, IM, __popc(lane & 22) & 1);  // w3: CNOT(3,6)
    predSwapK<2>(RE, IM, __popc(lane & 11) & 1);  // w4: CNOT(4,7)
    localCnot<8, 1>(RE, IM);                      // w5: CNOT(5,8)
    ctrlK_swpHalf<4>(RE, IM);                     // w6: CNOT(6,9)
    ctrlK_laneShfl<2, 29>(RE, IM);                // w7: CNOT(7,0)
    ctrlK_laneShfl<1, 14>(RE, IM);                // w8: CNOT(8,1)
    halfCtrl_laneShfl<7>(RE, IM);                 // w9: CNOT(9,2)
}

// ---------------------------------------------------------------------------
// Main kernel — one warp per block
// ---------------------------------------------------------------------------
__global__ void __launch_bounds__(32, 16)
vqc_kernel(const float* __restrict__ X, const float* __restrict__ bias,
           float* __restrict__ out, int B) {
    int warp = blockIdx.x;
    int lane = threadIdx.x;
    if (warp >= B) return;

    float x = (lane < NW) ? X[warp * NW + lane] : 0.0f;
    float mys, myc;
    sincosf(x * 0.78539816339744831f, &mys, &myc);

    u64 RE[16], IM[16];

    // Layer 1: direct product-state construction (M = I), then ring 1
    // (lane-lane block deferred: M := M1)
    buildInit(RE, IM, lane, myc, mys);
    ring1(RE, IM, lane);

    // Layer 2 (under M1): Gamma_0 + RY layer (lane block then local block)
    applyPhase(RE, IM, lane, 0);
    {
        const float2* cs = g_rycs + 0 * NW;
        ryLaneP<24, 16>(RE, IM, lane, cs[0].x, cs[0].y);
        ryLaneP<12, 24>(RE, IM, lane, cs[1].x, cs[1].y);
        ryLaneP<6, 28>(RE, IM, lane, cs[2].x, cs[2].y);
        ryLaneP<3, 30>(RE, IM, lane, cs[3].x, cs[3].y);
        ryLaneP<1, 31>(RE, IM, lane, cs[4].x, cs[4].y);
        ryLocalK<8>(RE, IM, cs[5].x, cs[5].y);
        ryLocalK<4>(RE, IM, cs[6].x, cs[6].y);
        ryLocalK<2>(RE, IM, cs[7].x, cs[7].y);
        ryLocalK<1>(RE, IM, cs[8].x, cs[8].y);
        ryHalf(RE, IM, cs[9].x, cs[9].y);
    }
    ring2(RE, IM, lane);   // (M := M2)

    // Layer 3 (under M2)
    applyPhase(RE, IM, lane, 1);
    {
        const float2* cs = g_rycs + 1 * NW;
        ryLaneP<30, 16>(RE, IM, lane, cs[0].x, cs[0].y);
        ryLaneP<15, 24>(RE, IM, lane, cs[1].x, cs[1].y);
        ryLaneP<7, 12>(RE, IM, lane, cs[2].x, cs[2].y);
        ryLaneP<3, 6>(RE, IM, lane, cs[3].x, cs[3].y);
        ryLaneP<1, 19>(RE, IM, lane, cs[4].x, cs[4].y);
        ryLocalK<8>(RE, IM, cs[5].x, cs[5].y);
        ryLocalK<4>(RE, IM, cs[6].x, cs[6].y);
        ryLocalK<2>(RE, IM, cs[7].x, cs[7].y);
        ryLocalK<1>(RE, IM, cs[8].x, cs[8].y);
        ryHalf(RE, IM, cs[9].x, cs[9].y);
    }
    ring3(RE, IM, lane);   // (M := M3)

    // Layer 4 (under M3): Gamma_2 + only the RYs on true wires {1,5,9}
    // (they carry the measured parity P = Z1 Z5 Z9 after ring-4 deferral;
    // other RYs commute with P and are dropped).
    applyPhase(RE, IM, lane, 2);
    {
        const float2* cs = g_rycs + 2 * NW;
        ryLaneP<14, 24>(RE, IM, lane, cs[1].x, cs[1].y);  // wire 1 under M3
        ryLocalK<8>(RE, IM, cs[5].x, cs[5].y);            // wire 5
        ryHalf(RE, IM, cs[9].x, cs[9].y);                 // wire 9
    }

    // Measurement: parity mask half ^ k_bit3 ^ parity(bufLane & 24)
    u64 accA = 0ull, accB = 0ull;
#pragma unroll
    for (int k = 0; k < 8; ++k)
        accA = ffma2(RE[k], RE[k], ffma2(IM[k], IM[k], accA));
#pragma unroll
    for (int k = 8; k < 16; ++k)
        accB = ffma2(RE[k], RE[k], ffma2(IM[k], IM[k], accB));
    float2 pA = unpk(accA), pB = unpk(accB);
    float z = (pA.x - pA.y) - (pB.x - pB.y);
    if (((lane >> 3) ^ (lane >> 4)) & 1) z = -z;
#pragma unroll
    for (int o = 16; o; o >>= 1) z += __shfl_xor_sync(FULL, z, o);
    if (lane == 0) out[warp] = z + bias[0];
}

// ---------------------------------------------------------------------------
extern "C" void kernel_launch(void* const* d_in, const int* in_sizes, int n_in,
                              void* d_out, int out_size) {
    const float* X = (const float*)d_in[0];
    const float* w = (const float*)d_in[1];
    const float* bias = (const float*)d_in[2];
    float* out = (float*)d_out;

    int B = in_sizes[0] / NW;

    prep_kernel<<<1, 1024>>>(w);

    vqc_kernel<<<B, 32>>>(X, bias, out, B);  // one warp per block
}